// round 14
// baseline (speedup 1.0000x reference)
#include <cuda_runtime.h>
#include <cuda_bf16.h>
#include <cuda_fp16.h>

#define N_NODES 50000
#define N_EDGES 800000
#define IN_DIM  256
#define HID     128
#define OUT_DIM 3
#define EDGE_DIM 4
#define N_LAYERS 4

// ---------------- static device scratch (no allocations allowed) -------------
__device__ float  g_x  [N_NODES * HID];     // fp32 node features (residual)
__device__ __half g_xh [N_NODES * HID];     // fp16 mirror of x (GEMM A operand)
__device__ __half g_P1h[N_NODES * HID];     // x @ W1 in fp16 (gathered by edges)
__device__ float  g_P2 [N_NODES * HID];     // x @ W2 + b_msg
__device__ int    g_deg[N_NODES];           // zero at load; re-zeroed by scan_add
__device__ int    g_rank[N_EDGES];          // edge rank within its dst bucket
__device__ int    g_off[N_NODES + 1];
__device__ int    g_blksum[64];
__device__ int    g_csr_src[N_EDGES];
__device__ float4 g_csr_ea [N_EDGES];
// Precomputed fp16 B fragments in per-lane mma order:
//   layer weights: [layer(4)][target(2)][n8(16)][kg(8)][lane(32)] uint2
//   input weights: [n8(16)][kg(16)][lane(32)] uint2
__device__ uint2  g_Bfrag  [N_LAYERS * 2 * 16 * 8 * 32];
__device__ uint2  g_BfragIn[16 * 16 * 32];

// ---------------- CSR build ---------------------------------------------------
__global__ void count_deg_kernel(const int* __restrict__ ei) {
    int e = blockIdx.x * blockDim.x + threadIdx.x;
    if (e < N_EDGES) {
        int dst = ei[N_EDGES + e];
        g_rank[e] = atomicAdd(&g_deg[dst], 1);   // rank doubles as fill position
    }
}

__global__ __launch_bounds__(1024)
void scan_local_kernel() {
    __shared__ int warp_sums[32];
    int tid  = threadIdx.x;
    int lane = tid & 31;
    int wid  = tid >> 5;
    int v = blockIdx.x * 1024 + tid;
    int d = (v < N_NODES) ? g_deg[v] : 0;
    int x = d;
    #pragma unroll
    for (int o = 1; o < 32; o <<= 1) {
        int y = __shfl_up_sync(0xFFFFFFFFu, x, o);
        if (lane >= o) x += y;
    }
    if (lane == 31) warp_sums[wid] = x;
    __syncthreads();
    if (wid == 0) {
        int w = warp_sums[lane];
        #pragma unroll
        for (int o = 1; o < 32; o <<= 1) {
            int y = __shfl_up_sync(0xFFFFFFFFu, w, o);
            if (lane >= o) w += y;
        }
        warp_sums[lane] = w;
    }
    __syncthreads();
    int prefix = (wid > 0) ? warp_sums[wid - 1] : 0;
    if (v < N_NODES) g_off[v] = prefix + x - d;
    if (tid == 1023) g_blksum[blockIdx.x] = prefix + x;
}

// adds block prefix AND re-zeroes g_deg for the next graph replay
__global__ __launch_bounds__(1024)
void scan_add_kernel() {
    __shared__ int base_s;
    int bid = blockIdx.x;
    if (threadIdx.x == 0) {
        int acc = 0;
        for (int i = 0; i < bid; ++i) acc += g_blksum[i];
        base_s = acc;
    }
    __syncthreads();
    int v = bid * 1024 + threadIdx.x;
    if (v < N_NODES) {
        g_off[v] += base_s;
        g_deg[v] = 0;                      // replaces the memset launch
    }
    if (v == 0) g_off[N_NODES] = N_EDGES;
}

__global__ void fill_csr_kernel(const int* __restrict__ ei,
                                const float* __restrict__ ea) {
    int e = blockIdx.x * blockDim.x + threadIdx.x;
    if (e >= N_EDGES) return;
    int src = ei[e];
    int dst = ei[N_EDGES + e];
    int pos = g_off[dst] + g_rank[e];      // atomic-free
    g_csr_src[pos] = src;
    g_csr_ea[pos]  = *(const float4*)(ea + (size_t)e * 4);
}

// ---------------- B-fragment precompute ---------------------------------------
__global__ void prep_bfrag_kernel(const float* __restrict__ W_in,
                                  const float* __restrict__ W_msg) {
    int idx  = blockIdx.x * blockDim.x + threadIdx.x;
    int lane = idx & 31;
    int rest = idx >> 5;
    const int NLAYER_ELEMS = N_LAYERS * 2 * 16 * 8;   // 1024 warp-slots
    if (rest < NLAYER_ELEMS) {
        int kg  = rest & 7;
        int n8  = (rest >> 3) & 15;
        int tgt = (rest >> 7) & 1;
        int l   = rest >> 8;
        const float* W = W_msg + (size_t)l * (2 * HID + EDGE_DIM) * HID
                               + (size_t)tgt * HID * HID;
        int n  = n8 * 8 + (lane >> 2);
        int k0 = kg * 16 + (lane & 3) * 2;
        __half2 b0 = __floats2half2_rn(W[(size_t)k0 * HID + n],
                                       W[(size_t)(k0 + 1) * HID + n]);
        __half2 b1 = __floats2half2_rn(W[(size_t)(k0 + 8) * HID + n],
                                       W[(size_t)(k0 + 9) * HID + n]);
        uint2 v;
        v.x = *(unsigned*)&b0;
        v.y = *(unsigned*)&b1;
        g_Bfrag[(size_t)rest * 32 + lane] = v;
    } else if (rest < NLAYER_ELEMS + 16 * 16) {
        int r2 = rest - NLAYER_ELEMS;
        int kg = r2 & 15;
        int n8 = r2 >> 4;
        int n  = n8 * 8 + (lane >> 2);
        int k0 = kg * 16 + (lane & 3) * 2;
        __half2 b0 = __floats2half2_rn(W_in[(size_t)k0 * HID + n],
                                       W_in[(size_t)(k0 + 1) * HID + n]);
        __half2 b1 = __floats2half2_rn(W_in[(size_t)(k0 + 8) * HID + n],
                                       W_in[(size_t)(k0 + 9) * HID + n]);
        uint2 v;
        v.x = *(unsigned*)&b0;
        v.y = *(unsigned*)&b1;
        g_BfragIn[(size_t)r2 * 32 + lane] = v;
    }
}

// ---------------- MMA helpers -------------------------------------------------
#define MMA_F16(c, a, b)                                                        \
    asm volatile(                                                               \
        "mma.sync.aligned.m16n8k16.row.col.f32.f16.f16.f32 "                    \
        "{%0,%1,%2,%3}, {%4,%5,%6,%7}, {%8,%9}, {%0,%1,%2,%3};\n"               \
        : "+f"((c)[0]), "+f"((c)[1]), "+f"((c)[2]), "+f"((c)[3])                \
        : "r"((a)[0]), "r"((a)[1]), "r"((a)[2]), "r"((a)[3]),                   \
          "r"((b)[0]), "r"((b)[1]))

__device__ __forceinline__ unsigned f2h2(float a, float b) {
    __half2 h = __floats2half2_rn(a, b);
    return *(unsigned*)&h;
}

// A fragment from fp32 global (used by gemm_in only, K=256)
__device__ __forceinline__ void loadAfrag(unsigned a[4], const float* __restrict__ A,
                                          int r, int kc, int K, int M) {
    const float* Ar = A + (size_t)r * K + kc;
    bool ok0 = r < M, ok1 = (r + 8) < M;
    float2 v0 = ok0 ? *(const float2*)(Ar)             : make_float2(0.f, 0.f);
    float2 v1 = ok1 ? *(const float2*)(Ar + 8 * K)     : make_float2(0.f, 0.f);
    float2 v2 = ok0 ? *(const float2*)(Ar + 8)         : make_float2(0.f, 0.f);
    float2 v3 = ok1 ? *(const float2*)(Ar + 8 * K + 8) : make_float2(0.f, 0.f);
    a[0] = f2h2(v0.x, v0.y);
    a[1] = f2h2(v1.x, v1.y);
    a[2] = f2h2(v2.x, v2.y);
    a[3] = f2h2(v3.x, v3.y);
}

// A fragment from fp16 global (layer GEMMs, K=128): 4 x LDG.32, zero converts
__device__ __forceinline__ void loadAfragH(unsigned a[4], const __half* __restrict__ Xh,
                                           int r, int kc, int M) {
    const __half* Ar = Xh + (size_t)r * HID + kc;
    bool ok0 = r < M, ok1 = (r + 8) < M;
    a[0] = ok0 ? *(const unsigned*)(Ar)             : 0u;
    a[1] = ok1 ? *(const unsigned*)(Ar + 8 * HID)     : 0u;
    a[2] = ok0 ? *(const unsigned*)(Ar + 8)         : 0u;
    a[3] = ok1 ? *(const unsigned*)(Ar + 8 * HID + 8) : 0u;
}

// ---------------- GEMMs: R8-proven 128-row tile, register-direct -------------
#define GBM 128

// input projection; writes x in fp32 AND its fp16 mirror
__global__ __launch_bounds__(256, 2)
void gemm_in_reg_kernel(const float* __restrict__ A,
                        const float* __restrict__ bias0,
                        float* __restrict__ C0, __half* __restrict__ C0h, int M) {
    int tid  = threadIdx.x;
    int lane = tid & 31;
    int warp = tid >> 5;
    int warpM = warp >> 1;
    int warpN = warp & 1;
    int rowBase = blockIdx.x * GBM;

    float c[2][8][4] = {};

    #pragma unroll
    for (int kg = 0; kg < 16; ++kg) {
        int kc = kg * 16 + (lane & 3) * 2;
        unsigned a[2][4];
        #pragma unroll
        for (int m = 0; m < 2; ++m) {
            int r = rowBase + warpM * 32 + m * 16 + (lane >> 2);
            loadAfrag(a[m], A, r, kc, IN_DIM, M);
        }
        uint2 b[8];
        #pragma unroll
        for (int n = 0; n < 8; ++n) {
            int n8 = warpN * 8 + n;
            b[n] = g_BfragIn[(size_t)((n8 * 16 + kg) * 32 + lane)];
        }
        #pragma unroll
        for (int m = 0; m < 2; ++m)
            #pragma unroll
            for (int n = 0; n < 8; ++n)
                MMA_F16(c[m][n], a[m], (unsigned*)&b[n]);
    }

    #pragma unroll
    for (int m = 0; m < 2; ++m) {
        int r0 = rowBase + warpM * 32 + m * 16 + (lane >> 2);
        #pragma unroll
        for (int n = 0; n < 8; ++n) {
            int col = warpN * 64 + n * 8 + (lane & 3) * 2;
            float o0 = c[m][n][0] + bias0[col];
            float o1 = c[m][n][1] + bias0[col + 1];
            float o2 = c[m][n][2] + bias0[col];
            float o3 = c[m][n][3] + bias0[col + 1];
            if (r0 < M) {
                *(float2*)(C0 + (size_t)r0 * 128 + col) = make_float2(o0, o1);
                *(__half2*)(C0h + (size_t)r0 * 128 + col) = __floats2half2_rn(o0, o1);
            }
            if (r0 + 8 < M) {
                *(float2*)(C0 + (size_t)(r0 + 8) * 128 + col) = make_float2(o2, o3);
                *(__half2*)(C0h + (size_t)(r0 + 8) * 128 + col) = __floats2half2_rn(o2, o3);
            }
        }
    }
}

// layer GEMM: A read directly from fp16 mirror (zero converts in mainloop)
__global__ __launch_bounds__(256, 2)
void gemm_layer_reg_kernel(const __half* __restrict__ Xh,
                           const uint2* __restrict__ BfragL,  // [2][16][8][32]
                           const float* __restrict__ bias1,
                           __half* __restrict__ C0, float* __restrict__ C1,
                           int M) {
    int tid  = threadIdx.x;
    int lane = tid & 31;
    int warp = tid >> 5;
    int warpM = warp >> 1;
    int warpN = warp & 1;
    int rowBase = blockIdx.x * GBM;

    #pragma unroll
    for (int t = 0; t < 2; ++t) {
        const uint2* Bf = BfragL + (size_t)t * (16 * 8 * 32);
        float c[2][8][4] = {};

        #pragma unroll
        for (int kg = 0; kg < 8; ++kg) {
            int kc = kg * 16 + (lane & 3) * 2;
            unsigned a[2][4];
            #pragma unroll
            for (int m = 0; m < 2; ++m) {
                int r = rowBase + warpM * 32 + m * 16 + (lane >> 2);
                loadAfragH(a[m], Xh, r, kc, M);
            }
            uint2 b[8];
            #pragma unroll
            for (int n = 0; n < 8; ++n) {
                int n8 = warpN * 8 + n;
                b[n] = Bf[(size_t)((n8 * 8 + kg) * 32 + lane)];
            }
            #pragma unroll
            for (int m = 0; m < 2; ++m)
                #pragma unroll
                for (int n = 0; n < 8; ++n)
                    MMA_F16(c[m][n], a[m], (unsigned*)&b[n]);
        }

        #pragma unroll
        for (int m = 0; m < 2; ++m) {
            int r0 = rowBase + warpM * 32 + m * 16 + (lane >> 2);
            #pragma unroll
            for (int n = 0; n < 8; ++n) {
                int col = warpN * 64 + n * 8 + (lane & 3) * 2;
                if (t == 0) {   // P1 -> fp16, no bias
                    if (r0 < M)
                        *(__half2*)(C0 + (size_t)r0 * 128 + col) =
                            __floats2half2_rn(c[m][n][0], c[m][n][1]);
                    if (r0 + 8 < M)
                        *(__half2*)(C0 + (size_t)(r0 + 8) * 128 + col) =
                            __floats2half2_rn(c[m][n][2], c[m][n][3]);
                } else {        // P2 -> fp32 + bias
                    float bb0 = bias1[col];
                    float bb1 = bias1[col + 1];
                    if (r0 < M)
                        *(float2*)(C1 + (size_t)r0 * 128 + col) =
                            make_float2(c[m][n][0] + bb0, c[m][n][1] + bb1);
                    if (r0 + 8 < M)
                        *(float2*)(C1 + (size_t)(r0 + 8) * 128 + col) =
                            make_float2(c[m][n][2] + bb0, c[m][n][3] + bb1);
                }
            }
        }
    }
}

// ---------------- edge message + aggregation (warp per dst node) -------------
#define EDGE_BLK 64

__device__ __forceinline__ float4 loadP1h(const __half* __restrict__ P1,
                                          int s, int c4) {
    uint2 raw = *(const uint2*)(P1 + (size_t)s * HID + c4);
    __half2 h0 = *reinterpret_cast<__half2*>(&raw.x);
    __half2 h1 = *reinterpret_cast<__half2*>(&raw.y);
    float2 f0 = __half22float2(h0);
    float2 f1 = __half22float2(h1);
    return make_float4(f0.x, f0.y, f1.x, f1.y);
}

#define EDGE_ONE(p1v, eav)                                                        \
    do {                                                                          \
        float mx = (p1v).x + p2.x + (eav).x * w0.x + (eav).y * w1.x +             \
                   (eav).z * w2.x + (eav).w * w3.x;                               \
        float my = (p1v).y + p2.y + (eav).x * w0.y + (eav).y * w1.y +             \
                   (eav).z * w2.y + (eav).w * w3.y;                               \
        float mz = (p1v).z + p2.z + (eav).x * w0.z + (eav).y * w1.z +             \
                   (eav).z * w2.z + (eav).w * w3.z;                               \
        float mw = (p1v).w + p2.w + (eav).x * w0.w + (eav).y * w1.w +             \
                   (eav).z * w2.w + (eav).w * w3.w;                               \
        acc.x += fmaxf(mx, 0.f); acc.y += fmaxf(my, 0.f);                         \
        acc.z += fmaxf(mz, 0.f); acc.w += fmaxf(mw, 0.f);                         \
    } while (0)

#define EDGE_ACCUM_BODY                                                           \
    float4 acc = make_float4(0.f, 0.f, 0.f, 0.f);                                 \
    int e0 = g_off[v];                                                            \
    int e1 = g_off[v + 1];                                                        \
    int e  = e0;                                                                  \
    for (; e + 7 < e1; e += 8) {                                                  \
        int    s[8];                                                              \
        float4 q[8], aa[8];                                                       \
        _Pragma("unroll")                                                         \
        for (int i = 0; i < 8; ++i) s[i] = __ldg(&g_csr_src[e + i]);              \
        _Pragma("unroll")                                                         \
        for (int i = 0; i < 8; ++i) q[i] = loadP1h(P1, s[i], c4);                 \
        _Pragma("unroll")                                                         \
        for (int i = 0; i < 8; ++i) aa[i] = g_csr_ea[e + i];                      \
        _Pragma("unroll")                                                         \
        for (int i = 0; i < 8; ++i) EDGE_ONE(q[i], aa[i]);                        \
    }                                                                             \
    for (; e + 3 < e1; e += 4) {                                                  \
        int    s[4];                                                              \
        float4 q[4], aa[4];                                                       \
        _Pragma("unroll")                                                         \
        for (int i = 0; i < 4; ++i) s[i] = __ldg(&g_csr_src[e + i]);              \
        _Pragma("unroll")                                                         \
        for (int i = 0; i < 4; ++i) q[i] = loadP1h(P1, s[i], c4);                 \
        _Pragma("unroll")                                                         \
        for (int i = 0; i < 4; ++i) aa[i] = g_csr_ea[e + i];                      \
        _Pragma("unroll")                                                         \
        for (int i = 0; i < 4; ++i) EDGE_ONE(q[i], aa[i]);                        \
    }                                                                             \
    for (; e < e1; ++e) {                                                         \
        int    s  = __ldg(&g_csr_src[e]);                                         \
        float4 q  = loadP1h(P1, s, c4);                                           \
        float4 aa = g_csr_ea[e];                                                  \
        EDGE_ONE(q, aa);                                                          \
    }

__global__ __launch_bounds__(EDGE_BLK)
void edge_msg_kernel(const __half* __restrict__ P1, const float* __restrict__ P2,
                     const float* __restrict__ W3 /* [4,128] */) {
    int warp = (blockIdx.x * blockDim.x + threadIdx.x) >> 5;
    int lane = threadIdx.x & 31;
    if (warp >= N_NODES) return;
    int v = warp;
    int c4 = lane * 4;

    float4 w0 = *(const float4*)(W3 + 0 * HID + c4);
    float4 w1 = *(const float4*)(W3 + 1 * HID + c4);
    float4 w2 = *(const float4*)(W3 + 2 * HID + c4);
    float4 w3 = *(const float4*)(W3 + 3 * HID + c4);
    float4 p2 = *(const float4*)(P2 + (size_t)v * HID + c4);

    EDGE_ACCUM_BODY

    float4 xv = *(float4*)(g_x + (size_t)v * HID + c4);
    xv.x += acc.x; xv.y += acc.y; xv.z += acc.z; xv.w += acc.w;
    *(float4*)(g_x + (size_t)v * HID + c4) = xv;
    // fp16 mirror for the next layer's GEMM A operand
    uint2 xh;
    xh.x = f2h2(xv.x, xv.y);
    xh.y = f2h2(xv.z, xv.w);
    *(uint2*)(g_xh + (size_t)v * HID + c4) = xh;
}

// last layer: fuse output projection; writes neither g_x nor g_xh
__global__ __launch_bounds__(EDGE_BLK)
void edge_msg_out_kernel(const __half* __restrict__ P1, const float* __restrict__ P2,
                         const float* __restrict__ W3,
                         const float* __restrict__ Wout,
                         const float* __restrict__ bout,
                         float* __restrict__ out) {
    int warp = (blockIdx.x * blockDim.x + threadIdx.x) >> 5;
    int lane = threadIdx.x & 31;
    if (warp >= N_NODES) return;
    int v = warp;
    int c4 = lane * 4;

    float4 w0 = *(const float4*)(W3 + 0 * HID + c4);
    float4 w1 = *(const float4*)(W3 + 1 * HID + c4);
    float4 w2 = *(const float4*)(W3 + 2 * HID + c4);
    float4 w3 = *(const float4*)(W3 + 3 * HID + c4);
    float4 p2 = *(const float4*)(P2 + (size_t)v * HID + c4);

    EDGE_ACCUM_BODY

    float4 xv = *(float4*)(g_x + (size_t)v * HID + c4);
    xv.x += acc.x; xv.y += acc.y; xv.z += acc.z; xv.w += acc.w;

    // output projection from in-register xv; lane owns dims c4..c4+3
    float s0 = xv.x * Wout[(c4 + 0) * 3 + 0] + xv.y * Wout[(c4 + 1) * 3 + 0]
             + xv.z * Wout[(c4 + 2) * 3 + 0] + xv.w * Wout[(c4 + 3) * 3 + 0];
    float s1 = xv.x * Wout[(c4 + 0) * 3 + 1] + xv.y * Wout[(c4 + 1) * 3 + 1]
             + xv.z * Wout[(c4 + 2) * 3 + 1] + xv.w * Wout[(c4 + 3) * 3 + 1];
    float s2 = xv.x * Wout[(c4 + 0) * 3 + 2] + xv.y * Wout[(c4 + 1) * 3 + 2]
             + xv.z * Wout[(c4 + 2) * 3 + 2] + xv.w * Wout[(c4 + 3) * 3 + 2];
    #pragma unroll
    for (int o = 16; o > 0; o >>= 1) {
        s0 += __shfl_xor_sync(0xFFFFFFFFu, s0, o);
        s1 += __shfl_xor_sync(0xFFFFFFFFu, s1, o);
        s2 += __shfl_xor_sync(0xFFFFFFFFu, s2, o);
    }
    if (lane == 0) {
        out[v * 3 + 0] = s0 + bout[0];
        out[v * 3 + 1] = s1 + bout[1];
        out[v * 3 + 2] = s2 + bout[2];
    }
}

// ---------------- launch ------------------------------------------------------
extern "C" void kernel_launch(void* const* d_in, const int* in_sizes, int n_in,
                              void* d_out, int out_size) {
    const float* h     = (const float*)d_in[0];
    const int*   ei    = (const int*)  d_in[1];
    const float* ea    = (const float*)d_in[2];
    const float* W_in  = (const float*)d_in[3];
    const float* b_in  = (const float*)d_in[4];
    const float* W_msg = (const float*)d_in[5];
    const float* b_msg = (const float*)d_in[6];
    const float* W_out = (const float*)d_in[7];
    const float* b_out = (const float*)d_in[8];
    float* out = (float*)d_out;

    float  *px, *pP2;
    __half *pP1h, *pXh;
    uint2  *pBfrag;
    cudaGetSymbolAddress((void**)&px,    g_x);
    cudaGetSymbolAddress((void**)&pXh,   g_xh);
    cudaGetSymbolAddress((void**)&pP1h,  g_P1h);
    cudaGetSymbolAddress((void**)&pP2,   g_P2);
    cudaGetSymbolAddress((void**)&pBfrag, g_Bfrag);

    const int EB = (N_EDGES + 255) / 256;
    const int SB = (N_NODES + 1023) / 1024;       // 49
    const int MT = (N_NODES + GBM - 1) / GBM;     // 391
    const int NODE_BLOCKS = (N_NODES * 32 + EDGE_BLK - 1) / EDGE_BLK;   // 25000

    prep_bfrag_kernel<<<160, 256>>>(W_in, W_msg);
    count_deg_kernel<<<EB, 256>>>(ei);            // g_deg zeroed by prior replay/load
    gemm_in_reg_kernel<<<MT, 256>>>(h, b_in, px, pXh, N_NODES);
    scan_local_kernel<<<SB, 1024>>>();
    // layer 0 GEMM (needs xh + Bfrag only)
    gemm_layer_reg_kernel<<<MT, 256>>>(pXh, pBfrag, b_msg, pP1h, pP2, N_NODES);
    scan_add_kernel<<<SB, 1024>>>();              // also re-zeroes g_deg
    fill_csr_kernel<<<EB, 256>>>(ei, ea);

    for (int l = 0; l < N_LAYERS; ++l) {
        const float* Wl = W_msg + (size_t)l * (2 * HID + EDGE_DIM) * HID;
        if (l > 0) {
            gemm_layer_reg_kernel<<<MT, 256>>>(pXh,
                                               pBfrag + (size_t)l * 2 * 16 * 8 * 32,
                                               b_msg + l * HID,
                                               pP1h, pP2, N_NODES);
        }
        if (l < N_LAYERS - 1) {
            edge_msg_kernel<<<NODE_BLOCKS, EDGE_BLK>>>(pP1h, pP2,
                                                       Wl + 2 * HID * HID);
        } else {
            edge_msg_out_kernel<<<NODE_BLOCKS, EDGE_BLK>>>(pP1h, pP2,
                                                           Wl + 2 * HID * HID,
                                                           W_out, b_out, out);
        }
    }
}

// round 15
// speedup vs baseline: 1.0008x; 1.0008x over previous
#include <cuda_runtime.h>
#include <cuda_bf16.h>
#include <cuda_fp16.h>

#define N_NODES 50000
#define N_EDGES 800000
#define IN_DIM  256
#define HID     128
#define OUT_DIM 3
#define EDGE_DIM 4
#define N_LAYERS 4

// ---------------- static device scratch (no allocations allowed) -------------
__device__ float  g_x  [N_NODES * HID];
__device__ __half g_P1h[N_NODES * HID];     // x @ W1 in fp16 (gathered by edges)
__device__ float  g_P2 [N_NODES * HID];     // x @ W2 + b_msg
__device__ int    g_deg[N_NODES];           // zero at load; re-zeroed by scan_add
__device__ int    g_rank[N_EDGES];          // edge rank within its dst bucket
__device__ int    g_off[N_NODES + 1];
__device__ int    g_blksum[64];
__device__ int    g_csr_src[N_EDGES];
__device__ float4 g_csr_ea [N_EDGES];
// Precomputed fp16 B fragments in per-lane mma order:
//   layer weights: [layer(4)][target(2)][n8(16)][kg(8)][lane(32)] uint2
//   input weights: [n8(16)][kg(16)][lane(32)] uint2
__device__ uint2  g_Bfrag  [N_LAYERS * 2 * 16 * 8 * 32];
__device__ uint2  g_BfragIn[16 * 16 * 32];

// ---------------- CSR build ---------------------------------------------------
// x4-batched: one int4 load of dst, 4 independent atomics, one int4 rank store.
__global__ void count_deg_kernel(const int* __restrict__ ei) {
    int base = (blockIdx.x * blockDim.x + threadIdx.x) * 4;
    if (base >= N_EDGES) return;   // N_EDGES % 4 == 0
    int4 d = *(const int4*)(ei + N_EDGES + base);
    int r0 = atomicAdd(&g_deg[d.x], 1);
    int r1 = atomicAdd(&g_deg[d.y], 1);
    int r2 = atomicAdd(&g_deg[d.z], 1);
    int r3 = atomicAdd(&g_deg[d.w], 1);
    *(int4*)(g_rank + base) = make_int4(r0, r1, r2, r3);
}

__global__ __launch_bounds__(1024)
void scan_local_kernel() {
    __shared__ int warp_sums[32];
    int tid  = threadIdx.x;
    int lane = tid & 31;
    int wid  = tid >> 5;
    int v = blockIdx.x * 1024 + tid;
    int d = (v < N_NODES) ? g_deg[v] : 0;
    int x = d;
    #pragma unroll
    for (int o = 1; o < 32; o <<= 1) {
        int y = __shfl_up_sync(0xFFFFFFFFu, x, o);
        if (lane >= o) x += y;
    }
    if (lane == 31) warp_sums[wid] = x;
    __syncthreads();
    if (wid == 0) {
        int w = warp_sums[lane];
        #pragma unroll
        for (int o = 1; o < 32; o <<= 1) {
            int y = __shfl_up_sync(0xFFFFFFFFu, w, o);
            if (lane >= o) w += y;
        }
        warp_sums[lane] = w;
    }
    __syncthreads();
    int prefix = (wid > 0) ? warp_sums[wid - 1] : 0;
    if (v < N_NODES) g_off[v] = prefix + x - d;
    if (tid == 1023) g_blksum[blockIdx.x] = prefix + x;
}

// adds block prefix AND re-zeroes g_deg for the next graph replay
__global__ __launch_bounds__(1024)
void scan_add_kernel() {
    __shared__ int base_s;
    int bid = blockIdx.x;
    if (threadIdx.x == 0) {
        int acc = 0;
        for (int i = 0; i < bid; ++i) acc += g_blksum[i];
        base_s = acc;
    }
    __syncthreads();
    int v = bid * 1024 + threadIdx.x;
    if (v < N_NODES) {
        g_off[v] += base_s;
        g_deg[v] = 0;                      // replaces the memset launch
    }
    if (v == 0) g_off[N_NODES] = N_EDGES;
}

// x2-batched: two independent scatter chains per thread.
__global__ void fill_csr_kernel(const int* __restrict__ ei,
                                const float* __restrict__ ea) {
    int base = (blockIdx.x * blockDim.x + threadIdx.x) * 2;
    if (base >= N_EDGES) return;   // N_EDGES % 2 == 0
    int2 src = *(const int2*)(ei + base);
    int2 dst = *(const int2*)(ei + N_EDGES + base);
    int2 rk  = *(const int2*)(g_rank + base);
    float4 a0 = *(const float4*)(ea + (size_t)base * 4);
    float4 a1 = *(const float4*)(ea + (size_t)(base + 1) * 4);
    int p0 = g_off[dst.x] + rk.x;
    int p1 = g_off[dst.y] + rk.y;
    g_csr_src[p0] = src.x;
    g_csr_src[p1] = src.y;
    g_csr_ea[p0]  = a0;
    g_csr_ea[p1]  = a1;
}

// ---------------- B-fragment precompute ---------------------------------------
__global__ void prep_bfrag_kernel(const float* __restrict__ W_in,
                                  const float* __restrict__ W_msg) {
    int idx  = blockIdx.x * blockDim.x + threadIdx.x;
    int lane = idx & 31;
    int rest = idx >> 5;
    const int NLAYER_ELEMS = N_LAYERS * 2 * 16 * 8;   // 1024 warp-slots
    if (rest < NLAYER_ELEMS) {
        int kg  = rest & 7;
        int n8  = (rest >> 3) & 15;
        int tgt = (rest >> 7) & 1;
        int l   = rest >> 8;
        const float* W = W_msg + (size_t)l * (2 * HID + EDGE_DIM) * HID
                               + (size_t)tgt * HID * HID;
        int n  = n8 * 8 + (lane >> 2);
        int k0 = kg * 16 + (lane & 3) * 2;
        __half2 b0 = __floats2half2_rn(W[(size_t)k0 * HID + n],
                                       W[(size_t)(k0 + 1) * HID + n]);
        __half2 b1 = __floats2half2_rn(W[(size_t)(k0 + 8) * HID + n],
                                       W[(size_t)(k0 + 9) * HID + n]);
        uint2 v;
        v.x = *(unsigned*)&b0;
        v.y = *(unsigned*)&b1;
        g_Bfrag[(size_t)rest * 32 + lane] = v;
    } else if (rest < NLAYER_ELEMS + 16 * 16) {
        int r2 = rest - NLAYER_ELEMS;
        int kg = r2 & 15;
        int n8 = r2 >> 4;
        int n  = n8 * 8 + (lane >> 2);
        int k0 = kg * 16 + (lane & 3) * 2;
        __half2 b0 = __floats2half2_rn(W_in[(size_t)k0 * HID + n],
                                       W_in[(size_t)(k0 + 1) * HID + n]);
        __half2 b1 = __floats2half2_rn(W_in[(size_t)(k0 + 8) * HID + n],
                                       W_in[(size_t)(k0 + 9) * HID + n]);
        uint2 v;
        v.x = *(unsigned*)&b0;
        v.y = *(unsigned*)&b1;
        g_BfragIn[(size_t)r2 * 32 + lane] = v;
    }
}

// ---------------- MMA helpers -------------------------------------------------
#define MMA_F16(c, a, b)                                                        \
    asm volatile(                                                               \
        "mma.sync.aligned.m16n8k16.row.col.f32.f16.f16.f32 "                    \
        "{%0,%1,%2,%3}, {%4,%5,%6,%7}, {%8,%9}, {%0,%1,%2,%3};\n"               \
        : "+f"((c)[0]), "+f"((c)[1]), "+f"((c)[2]), "+f"((c)[3])                \
        : "r"((a)[0]), "r"((a)[1]), "r"((a)[2]), "r"((a)[3]),                   \
          "r"((b)[0]), "r"((b)[1]))

__device__ __forceinline__ unsigned f2h2(float a, float b) {
    __half2 h = __floats2half2_rn(a, b);
    return *(unsigned*)&h;
}

__device__ __forceinline__ void loadAfrag(unsigned a[4], const float* __restrict__ A,
                                          int r, int kc, int K, int M) {
    const float* Ar = A + (size_t)r * K + kc;
    bool ok0 = r < M, ok1 = (r + 8) < M;
    float2 v0 = ok0 ? *(const float2*)(Ar)             : make_float2(0.f, 0.f);
    float2 v1 = ok1 ? *(const float2*)(Ar + 8 * K)     : make_float2(0.f, 0.f);
    float2 v2 = ok0 ? *(const float2*)(Ar + 8)         : make_float2(0.f, 0.f);
    float2 v3 = ok1 ? *(const float2*)(Ar + 8 * K + 8) : make_float2(0.f, 0.f);
    a[0] = f2h2(v0.x, v0.y);
    a[1] = f2h2(v1.x, v1.y);
    a[2] = f2h2(v2.x, v2.y);
    a[3] = f2h2(v3.x, v3.y);
}

// ---------------- GEMMs: R8-proven 128-row tile, register-direct -------------
#define GBM 128

__global__ __launch_bounds__(256, 2)
void gemm_in_reg_kernel(const float* __restrict__ A,
                        const float* __restrict__ bias0,
                        float* __restrict__ C0, int M) {
    int tid  = threadIdx.x;
    int lane = tid & 31;
    int warp = tid >> 5;
    int warpM = warp >> 1;
    int warpN = warp & 1;
    int rowBase = blockIdx.x * GBM;

    float c[2][8][4] = {};

    #pragma unroll
    for (int kg = 0; kg < 16; ++kg) {
        int kc = kg * 16 + (lane & 3) * 2;
        unsigned a[2][4];
        #pragma unroll
        for (int m = 0; m < 2; ++m) {
            int r = rowBase + warpM * 32 + m * 16 + (lane >> 2);
            loadAfrag(a[m], A, r, kc, IN_DIM, M);
        }
        uint2 b[8];
        #pragma unroll
        for (int n = 0; n < 8; ++n) {
            int n8 = warpN * 8 + n;
            b[n] = g_BfragIn[(size_t)((n8 * 16 + kg) * 32 + lane)];
        }
        #pragma unroll
        for (int m = 0; m < 2; ++m)
            #pragma unroll
            for (int n = 0; n < 8; ++n)
                MMA_F16(c[m][n], a[m], (unsigned*)&b[n]);
    }

    #pragma unroll
    for (int m = 0; m < 2; ++m) {
        int r0 = rowBase + warpM * 32 + m * 16 + (lane >> 2);
        #pragma unroll
        for (int n = 0; n < 8; ++n) {
            int col = warpN * 64 + n * 8 + (lane & 3) * 2;
            float bb0 = bias0[col];
            float bb1 = bias0[col + 1];
            if (r0 < M)
                *(float2*)(C0 + (size_t)r0 * 128 + col) =
                    make_float2(c[m][n][0] + bb0, c[m][n][1] + bb1);
            if (r0 + 8 < M)
                *(float2*)(C0 + (size_t)(r0 + 8) * 128 + col) =
                    make_float2(c[m][n][2] + bb0, c[m][n][3] + bb1);
        }
    }
}

__global__ __launch_bounds__(256, 2)
void gemm_layer_reg_kernel(const float* __restrict__ A,
                           const uint2* __restrict__ BfragL,  // [2][16][8][32]
                           const float* __restrict__ bias1,
                           __half* __restrict__ C0, float* __restrict__ C1,
                           int M) {
    int tid  = threadIdx.x;
    int lane = tid & 31;
    int warp = tid >> 5;
    int warpM = warp >> 1;
    int warpN = warp & 1;
    int rowBase = blockIdx.x * GBM;

    #pragma unroll
    for (int t = 0; t < 2; ++t) {
        const uint2* Bf = BfragL + (size_t)t * (16 * 8 * 32);
        float c[2][8][4] = {};

        #pragma unroll
        for (int kg = 0; kg < 8; ++kg) {
            int kc = kg * 16 + (lane & 3) * 2;
            unsigned a[2][4];
            #pragma unroll
            for (int m = 0; m < 2; ++m) {
                int r = rowBase + warpM * 32 + m * 16 + (lane >> 2);
                loadAfrag(a[m], A, r, kc, HID, M);
            }
            uint2 b[8];
            #pragma unroll
            for (int n = 0; n < 8; ++n) {
                int n8 = warpN * 8 + n;
                b[n] = Bf[(size_t)((n8 * 8 + kg) * 32 + lane)];
            }
            #pragma unroll
            for (int m = 0; m < 2; ++m)
                #pragma unroll
                for (int n = 0; n < 8; ++n)
                    MMA_F16(c[m][n], a[m], (unsigned*)&b[n]);
        }

        #pragma unroll
        for (int m = 0; m < 2; ++m) {
            int r0 = rowBase + warpM * 32 + m * 16 + (lane >> 2);
            #pragma unroll
            for (int n = 0; n < 8; ++n) {
                int col = warpN * 64 + n * 8 + (lane & 3) * 2;
                if (t == 0) {   // P1 -> fp16, no bias
                    if (r0 < M)
                        *(__half2*)(C0 + (size_t)r0 * 128 + col) =
                            __floats2half2_rn(c[m][n][0], c[m][n][1]);
                    if (r0 + 8 < M)
                        *(__half2*)(C0 + (size_t)(r0 + 8) * 128 + col) =
                            __floats2half2_rn(c[m][n][2], c[m][n][3]);
                } else {        // P2 -> fp32 + bias
                    float bb0 = bias1[col];
                    float bb1 = bias1[col + 1];
                    if (r0 < M)
                        *(float2*)(C1 + (size_t)r0 * 128 + col) =
                            make_float2(c[m][n][0] + bb0, c[m][n][1] + bb1);
                    if (r0 + 8 < M)
                        *(float2*)(C1 + (size_t)(r0 + 8) * 128 + col) =
                            make_float2(c[m][n][2] + bb0, c[m][n][3] + bb1);
                }
            }
        }
    }
}

// ---------------- edge message + aggregation (warp per dst node) -------------
#define EDGE_BLK 64

__device__ __forceinline__ float4 loadP1h(const __half* __restrict__ P1,
                                          int s, int c4) {
    uint2 raw = *(const uint2*)(P1 + (size_t)s * HID + c4);
    __half2 h0 = *reinterpret_cast<__half2*>(&raw.x);
    __half2 h1 = *reinterpret_cast<__half2*>(&raw.y);
    float2 f0 = __half22float2(h0);
    float2 f1 = __half22float2(h1);
    return make_float4(f0.x, f0.y, f1.x, f1.y);
}

#define EDGE_ONE(p1v, eav)                                                        \
    do {                                                                          \
        float mx = (p1v).x + p2.x + (eav).x * w0.x + (eav).y * w1.x +             \
                   (eav).z * w2.x + (eav).w * w3.x;                               \
        float my = (p1v).y + p2.y + (eav).x * w0.y + (eav).y * w1.y +             \
                   (eav).z * w2.y + (eav).w * w3.y;                               \
        float mz = (p1v).z + p2.z + (eav).x * w0.z + (eav).y * w1.z +             \
                   (eav).z * w2.z + (eav).w * w3.z;                               \
        float mw = (p1v).w + p2.w + (eav).x * w0.w + (eav).y * w1.w +             \
                   (eav).z * w2.w + (eav).w * w3.w;                               \
        acc.x += fmaxf(mx, 0.f); acc.y += fmaxf(my, 0.f);                         \
        acc.z += fmaxf(mz, 0.f); acc.w += fmaxf(mw, 0.f);                         \
    } while (0)

#define EDGE_ACCUM_BODY                                                           \
    float4 acc = make_float4(0.f, 0.f, 0.f, 0.f);                                 \
    int e0 = g_off[v];                                                            \
    int e1 = g_off[v + 1];                                                        \
    int e  = e0;                                                                  \
    for (; e + 7 < e1; e += 8) {                                                  \
        int    s[8];                                                              \
        float4 q[8], aa[8];                                                       \
        _Pragma("unroll")                                                         \
        for (int i = 0; i < 8; ++i) s[i] = __ldg(&g_csr_src[e + i]);              \
        _Pragma("unroll")                                                         \
        for (int i = 0; i < 8; ++i) q[i] = loadP1h(P1, s[i], c4);                 \
        _Pragma("unroll")                                                         \
        for (int i = 0; i < 8; ++i) aa[i] = g_csr_ea[e + i];                      \
        _Pragma("unroll")                                                         \
        for (int i = 0; i < 8; ++i) EDGE_ONE(q[i], aa[i]);                        \
    }                                                                             \
    for (; e + 3 < e1; e += 4) {                                                  \
        int    s[4];                                                              \
        float4 q[4], aa[4];                                                       \
        _Pragma("unroll")                                                         \
        for (int i = 0; i < 4; ++i) s[i] = __ldg(&g_csr_src[e + i]);              \
        _Pragma("unroll")                                                         \
        for (int i = 0; i < 4; ++i) q[i] = loadP1h(P1, s[i], c4);                 \
        _Pragma("unroll")                                                         \
        for (int i = 0; i < 4; ++i) aa[i] = g_csr_ea[e + i];                      \
        _Pragma("unroll")                                                         \
        for (int i = 0; i < 4; ++i) EDGE_ONE(q[i], aa[i]);                        \
    }                                                                             \
    for (; e < e1; ++e) {                                                         \
        int    s  = __ldg(&g_csr_src[e]);                                         \
        float4 q  = loadP1h(P1, s, c4);                                           \
        float4 aa = g_csr_ea[e];                                                  \
        EDGE_ONE(q, aa);                                                          \
    }

__global__ __launch_bounds__(EDGE_BLK)
void edge_msg_kernel(const __half* __restrict__ P1, const float* __restrict__ P2,
                     const float* __restrict__ W3 /* [4,128] */) {
    int warp = (blockIdx.x * blockDim.x + threadIdx.x) >> 5;
    int lane = threadIdx.x & 31;
    if (warp >= N_NODES) return;
    int v = warp;
    int c4 = lane * 4;

    float4 w0 = *(const float4*)(W3 + 0 * HID + c4);
    float4 w1 = *(const float4*)(W3 + 1 * HID + c4);
    float4 w2 = *(const float4*)(W3 + 2 * HID + c4);
    float4 w3 = *(const float4*)(W3 + 3 * HID + c4);
    float4 p2 = *(const float4*)(P2 + (size_t)v * HID + c4);

    EDGE_ACCUM_BODY

    float4 xv = *(float4*)(g_x + (size_t)v * HID + c4);
    xv.x += acc.x; xv.y += acc.y; xv.z += acc.z; xv.w += acc.w;
    *(float4*)(g_x + (size_t)v * HID + c4) = xv;
}

// last layer: fuse output projection; never writes g_x (saves full RW pass)
__global__ __launch_bounds__(EDGE_BLK)
void edge_msg_out_kernel(const __half* __restrict__ P1, const float* __restrict__ P2,
                         const float* __restrict__ W3,
                         const float* __restrict__ Wout,
                         const float* __restrict__ bout,
                         float* __restrict__ out) {
    int warp = (blockIdx.x * blockDim.x + threadIdx.x) >> 5;
    int lane = threadIdx.x & 31;
    if (warp >= N_NODES) return;
    int v = warp;
    int c4 = lane * 4;

    float4 w0 = *(const float4*)(W3 + 0 * HID + c4);
    float4 w1 = *(const float4*)(W3 + 1 * HID + c4);
    float4 w2 = *(const float4*)(W3 + 2 * HID + c4);
    float4 w3 = *(const float4*)(W3 + 3 * HID + c4);
    float4 p2 = *(const float4*)(P2 + (size_t)v * HID + c4);

    EDGE_ACCUM_BODY

    float4 xv = *(float4*)(g_x + (size_t)v * HID + c4);
    xv.x += acc.x; xv.y += acc.y; xv.z += acc.z; xv.w += acc.w;

    // output projection from in-register xv; lane owns dims c4..c4+3
    float s0 = xv.x * Wout[(c4 + 0) * 3 + 0] + xv.y * Wout[(c4 + 1) * 3 + 0]
             + xv.z * Wout[(c4 + 2) * 3 + 0] + xv.w * Wout[(c4 + 3) * 3 + 0];
    float s1 = xv.x * Wout[(c4 + 0) * 3 + 1] + xv.y * Wout[(c4 + 1) * 3 + 1]
             + xv.z * Wout[(c4 + 2) * 3 + 1] + xv.w * Wout[(c4 + 3) * 3 + 1];
    float s2 = xv.x * Wout[(c4 + 0) * 3 + 2] + xv.y * Wout[(c4 + 1) * 3 + 2]
             + xv.z * Wout[(c4 + 2) * 3 + 2] + xv.w * Wout[(c4 + 3) * 3 + 2];
    #pragma unroll
    for (int o = 16; o > 0; o >>= 1) {
        s0 += __shfl_xor_sync(0xFFFFFFFFu, s0, o);
        s1 += __shfl_xor_sync(0xFFFFFFFFu, s1, o);
        s2 += __shfl_xor_sync(0xFFFFFFFFu, s2, o);
    }
    if (lane == 0) {
        out[v * 3 + 0] = s0 + bout[0];
        out[v * 3 + 1] = s1 + bout[1];
        out[v * 3 + 2] = s2 + bout[2];
    }
}

// ---------------- launch ------------------------------------------------------
extern "C" void kernel_launch(void* const* d_in, const int* in_sizes, int n_in,
                              void* d_out, int out_size) {
    const float* h     = (const float*)d_in[0];
    const int*   ei    = (const int*)  d_in[1];
    const float* ea    = (const float*)d_in[2];
    const float* W_in  = (const float*)d_in[3];
    const float* b_in  = (const float*)d_in[4];
    const float* W_msg = (const float*)d_in[5];
    const float* b_msg = (const float*)d_in[6];
    const float* W_out = (const float*)d_in[7];
    const float* b_out = (const float*)d_in[8];
    float* out = (float*)d_out;

    float  *px, *pP2;
    __half *pP1h;
    uint2  *pBfrag;
    cudaGetSymbolAddress((void**)&px,    g_x);
    cudaGetSymbolAddress((void**)&pP1h,  g_P1h);
    cudaGetSymbolAddress((void**)&pP2,   g_P2);
    cudaGetSymbolAddress((void**)&pBfrag, g_Bfrag);

    const int CB = (N_EDGES / 4 + 255) / 256;     // 782  (count, x4)
    const int FB = (N_EDGES / 2 + 255) / 256;     // 1563 (fill, x2)
    const int SB = (N_NODES + 1023) / 1024;       // 49
    const int MT = (N_NODES + GBM - 1) / GBM;     // 391
    const int NODE_BLOCKS = (N_NODES * 32 + EDGE_BLK - 1) / EDGE_BLK;   // 25000

    // Interleave independent CSR and GEMM chains (R13-proven order).
    prep_bfrag_kernel<<<160, 256>>>(W_in, W_msg);
    count_deg_kernel<<<CB, 256>>>(ei);            // g_deg zeroed by prior replay/load
    gemm_in_reg_kernel<<<MT, 256>>>(h, b_in, px, N_NODES);
    scan_local_kernel<<<SB, 1024>>>();
    gemm_layer_reg_kernel<<<MT, 256>>>(px, pBfrag, b_msg, pP1h, pP2, N_NODES);
    scan_add_kernel<<<SB, 1024>>>();              // also re-zeroes g_deg
    fill_csr_kernel<<<FB, 256>>>(ei, ea);

    for (int l = 0; l < N_LAYERS; ++l) {
        const float* Wl = W_msg + (size_t)l * (2 * HID + EDGE_DIM) * HID;
        if (l > 0) {
            gemm_layer_reg_kernel<<<MT, 256>>>(px,
                                               pBfrag + (size_t)l * 2 * 16 * 8 * 32,
                                               b_msg + l * HID,
                                               pP1h, pP2, N_NODES);
        }
        if (l < N_LAYERS - 1) {
            edge_msg_kernel<<<NODE_BLOCKS, EDGE_BLK>>>(pP1h, pP2,
                                                       Wl + 2 * HID * HID);
        } else {
            edge_msg_out_kernel<<<NODE_BLOCKS, EDGE_BLK>>>(pP1h, pP2,
                                                           Wl + 2 * HID * HID,
                                                           W_out, b_out, out);
        }
    }
}

// round 16
// speedup vs baseline: 1.0463x; 1.0454x over previous
#include <cuda_runtime.h>
#include <cuda_bf16.h>
#include <cuda_fp16.h>

#define N_NODES 50000
#define N_EDGES 800000
#define IN_DIM  256
#define HID     128
#define OUT_DIM 3
#define EDGE_DIM 4
#define N_LAYERS 4

// ---------------- static device scratch (no allocations allowed) -------------
__device__ float  g_x  [N_NODES * HID];
__device__ __half g_P1h[N_NODES * HID];     // x @ W1 in fp16 (gathered by edges)
__device__ float  g_P2 [N_NODES * HID];     // x @ W2 + b_msg
__device__ int    g_deg[N_NODES];           // zero at load; re-zeroed by scan_add
__device__ int    g_rank[N_EDGES];          // edge rank within its dst bucket
__device__ int    g_off[N_NODES + 1];
__device__ int    g_blksum[64];
__device__ int    g_csr_src[N_EDGES];
__device__ float4 g_csr_ea [N_EDGES];
// Precomputed fp16 B fragments in per-lane mma order
__device__ uint2  g_Bfrag  [N_LAYERS * 2 * 16 * 8 * 32];
__device__ uint2  g_BfragIn[16 * 16 * 32];

// ---------------- CSR build (R13-proven) --------------------------------------
__global__ void count_deg_kernel(const int* __restrict__ ei) {
    int e = blockIdx.x * blockDim.x + threadIdx.x;
    if (e < N_EDGES) {
        int dst = ei[N_EDGES + e];
        g_rank[e] = atomicAdd(&g_deg[dst], 1);   // rank doubles as fill position
    }
}

__global__ __launch_bounds__(1024)
void scan_local_kernel() {
    __shared__ int warp_sums[32];
    int tid  = threadIdx.x;
    int lane = tid & 31;
    int wid  = tid >> 5;
    int v = blockIdx.x * 1024 + tid;
    int d = (v < N_NODES) ? g_deg[v] : 0;
    int x = d;
    #pragma unroll
    for (int o = 1; o < 32; o <<= 1) {
        int y = __shfl_up_sync(0xFFFFFFFFu, x, o);
        if (lane >= o) x += y;
    }
    if (lane == 31) warp_sums[wid] = x;
    __syncthreads();
    if (wid == 0) {
        int w = warp_sums[lane];
        #pragma unroll
        for (int o = 1; o < 32; o <<= 1) {
            int y = __shfl_up_sync(0xFFFFFFFFu, w, o);
            if (lane >= o) w += y;
        }
        warp_sums[lane] = w;
    }
    __syncthreads();
    int prefix = (wid > 0) ? warp_sums[wid - 1] : 0;
    if (v < N_NODES) g_off[v] = prefix + x - d;
    if (tid == 1023) g_blksum[blockIdx.x] = prefix + x;
}

// adds block prefix AND re-zeroes g_deg for the next graph replay
__global__ __launch_bounds__(1024)
void scan_add_kernel() {
    __shared__ int base_s;
    int bid = blockIdx.x;
    if (threadIdx.x == 0) {
        int acc = 0;
        for (int i = 0; i < bid; ++i) acc += g_blksum[i];
        base_s = acc;
    }
    __syncthreads();
    int v = bid * 1024 + threadIdx.x;
    if (v < N_NODES) {
        g_off[v] += base_s;
        g_deg[v] = 0;                      // replaces the memset launch
    }
    if (v == 0) g_off[N_NODES] = N_EDGES;
}

__global__ void fill_csr_kernel(const int* __restrict__ ei,
                                const float* __restrict__ ea) {
    int e = blockIdx.x * blockDim.x + threadIdx.x;
    if (e >= N_EDGES) return;
    int src = ei[e];
    int dst = ei[N_EDGES + e];
    int pos = g_off[dst] + g_rank[e];      // atomic-free
    g_csr_src[pos] = src;
    g_csr_ea[pos]  = *(const float4*)(ea + (size_t)e * 4);
}

// ---------------- B-fragment precompute ---------------------------------------
__global__ void prep_bfrag_kernel(const float* __restrict__ W_in,
                                  const float* __restrict__ W_msg) {
    int idx  = blockIdx.x * blockDim.x + threadIdx.x;
    int lane = idx & 31;
    int rest = idx >> 5;
    const int NLAYER_ELEMS = N_LAYERS * 2 * 16 * 8;   // 1024 warp-slots
    if (rest < NLAYER_ELEMS) {
        int kg  = rest & 7;
        int n8  = (rest >> 3) & 15;
        int tgt = (rest >> 7) & 1;
        int l   = rest >> 8;
        const float* W = W_msg + (size_t)l * (2 * HID + EDGE_DIM) * HID
                               + (size_t)tgt * HID * HID;
        int n  = n8 * 8 + (lane >> 2);
        int k0 = kg * 16 + (lane & 3) * 2;
        __half2 b0 = __floats2half2_rn(W[(size_t)k0 * HID + n],
                                       W[(size_t)(k0 + 1) * HID + n]);
        __half2 b1 = __floats2half2_rn(W[(size_t)(k0 + 8) * HID + n],
                                       W[(size_t)(k0 + 9) * HID + n]);
        uint2 v;
        v.x = *(unsigned*)&b0;
        v.y = *(unsigned*)&b1;
        g_Bfrag[(size_t)rest * 32 + lane] = v;
    } else if (rest < NLAYER_ELEMS + 16 * 16) {
        int r2 = rest - NLAYER_ELEMS;
        int kg = r2 & 15;
        int n8 = r2 >> 4;
        int n  = n8 * 8 + (lane >> 2);
        int k0 = kg * 16 + (lane & 3) * 2;
        __half2 b0 = __floats2half2_rn(W_in[(size_t)k0 * HID + n],
                                       W_in[(size_t)(k0 + 1) * HID + n]);
        __half2 b1 = __floats2half2_rn(W_in[(size_t)(k0 + 8) * HID + n],
                                       W_in[(size_t)(k0 + 9) * HID + n]);
        uint2 v;
        v.x = *(unsigned*)&b0;
        v.y = *(unsigned*)&b1;
        g_BfragIn[(size_t)r2 * 32 + lane] = v;
    }
}

// ---------------- MMA helpers -------------------------------------------------
#define MMA_F16(c, a, b)                                                        \
    asm volatile(                                                               \
        "mma.sync.aligned.m16n8k16.row.col.f32.f16.f16.f32 "                    \
        "{%0,%1,%2,%3}, {%4,%5,%6,%7}, {%8,%9}, {%0,%1,%2,%3};\n"               \
        : "+f"((c)[0]), "+f"((c)[1]), "+f"((c)[2]), "+f"((c)[3])                \
        : "r"((a)[0]), "r"((a)[1]), "r"((a)[2]), "r"((a)[3]),                   \
          "r"((b)[0]), "r"((b)[1]))

__device__ __forceinline__ unsigned f2h2(float a, float b) {
    __half2 h = __floats2half2_rn(a, b);
    return *(unsigned*)&h;
}

__device__ __forceinline__ void loadAfrag(unsigned a[4], const float* __restrict__ A,
                                          int r, int kc, int K, int M) {
    const float* Ar = A + (size_t)r * K + kc;
    bool ok0 = r < M, ok1 = (r + 8) < M;
    float2 v0 = ok0 ? *(const float2*)(Ar)             : make_float2(0.f, 0.f);
    float2 v1 = ok1 ? *(const float2*)(Ar + 8 * K)     : make_float2(0.f, 0.f);
    float2 v2 = ok0 ? *(const float2*)(Ar + 8)         : make_float2(0.f, 0.f);
    float2 v3 = ok1 ? *(const float2*)(Ar + 8 * K + 8) : make_float2(0.f, 0.f);
    a[0] = f2h2(v0.x, v0.y);
    a[1] = f2h2(v1.x, v1.y);
    a[2] = f2h2(v2.x, v2.y);
    a[3] = f2h2(v3.x, v3.y);
}

// ---------------- GEMMs: R8-proven 128-row tile, register-direct -------------
#define GBM 128

__global__ __launch_bounds__(256, 2)
void gemm_in_reg_kernel(const float* __restrict__ A,
                        const float* __restrict__ bias0,
                        float* __restrict__ C0, int M) {
    int tid  = threadIdx.x;
    int lane = tid & 31;
    int warp = tid >> 5;
    int warpM = warp >> 1;
    int warpN = warp & 1;
    int rowBase = blockIdx.x * GBM;

    float c[2][8][4] = {};

    #pragma unroll
    for (int kg = 0; kg < 16; ++kg) {
        int kc = kg * 16 + (lane & 3) * 2;
        unsigned a[2][4];
        #pragma unroll
        for (int m = 0; m < 2; ++m) {
            int r = rowBase + warpM * 32 + m * 16 + (lane >> 2);
            loadAfrag(a[m], A, r, kc, IN_DIM, M);
        }
        uint2 b[8];
        #pragma unroll
        for (int n = 0; n < 8; ++n) {
            int n8 = warpN * 8 + n;
            b[n] = g_BfragIn[(size_t)((n8 * 16 + kg) * 32 + lane)];
        }
        #pragma unroll
        for (int m = 0; m < 2; ++m)
            #pragma unroll
            for (int n = 0; n < 8; ++n)
                MMA_F16(c[m][n], a[m], (unsigned*)&b[n]);
    }

    #pragma unroll
    for (int m = 0; m < 2; ++m) {
        int r0 = rowBase + warpM * 32 + m * 16 + (lane >> 2);
        #pragma unroll
        for (int n = 0; n < 8; ++n) {
            int col = warpN * 64 + n * 8 + (lane & 3) * 2;
            float bb0 = bias0[col];
            float bb1 = bias0[col + 1];
            if (r0 < M)
                *(float2*)(C0 + (size_t)r0 * 128 + col) =
                    make_float2(c[m][n][0] + bb0, c[m][n][1] + bb1);
            if (r0 + 8 < M)
                *(float2*)(C0 + (size_t)(r0 + 8) * 128 + col) =
                    make_float2(c[m][n][2] + bb0, c[m][n][3] + bb1);
        }
    }
}

__global__ __launch_bounds__(256, 2)
void gemm_layer_reg_kernel(const float* __restrict__ A,
                           const uint2* __restrict__ BfragL,  // [2][16][8][32]
                           const float* __restrict__ bias1,
                           __half* __restrict__ C0, float* __restrict__ C1,
                           int M) {
    int tid  = threadIdx.x;
    int lane = tid & 31;
    int warp = tid >> 5;
    int warpM = warp >> 1;
    int warpN = warp & 1;
    int rowBase = blockIdx.x * GBM;

    #pragma unroll
    for (int t = 0; t < 2; ++t) {
        const uint2* Bf = BfragL + (size_t)t * (16 * 8 * 32);
        float c[2][8][4] = {};

        #pragma unroll
        for (int kg = 0; kg < 8; ++kg) {
            int kc = kg * 16 + (lane & 3) * 2;
            unsigned a[2][4];
            #pragma unroll
            for (int m = 0; m < 2; ++m) {
                int r = rowBase + warpM * 32 + m * 16 + (lane >> 2);
                loadAfrag(a[m], A, r, kc, HID, M);
            }
            uint2 b[8];
            #pragma unroll
            for (int n = 0; n < 8; ++n) {
                int n8 = warpN * 8 + n;
                b[n] = Bf[(size_t)((n8 * 8 + kg) * 32 + lane)];
            }
            #pragma unroll
            for (int m = 0; m < 2; ++m)
                #pragma unroll
                for (int n = 0; n < 8; ++n)
                    MMA_F16(c[m][n], a[m], (unsigned*)&b[n]);
        }

        #pragma unroll
        for (int m = 0; m < 2; ++m) {
            int r0 = rowBase + warpM * 32 + m * 16 + (lane >> 2);
            #pragma unroll
            for (int n = 0; n < 8; ++n) {
                int col = warpN * 64 + n * 8 + (lane & 3) * 2;
                if (t == 0) {   // P1 -> fp16, no bias
                    if (r0 < M)
                        *(__half2*)(C0 + (size_t)r0 * 128 + col) =
                            __floats2half2_rn(c[m][n][0], c[m][n][1]);
                    if (r0 + 8 < M)
                        *(__half2*)(C0 + (size_t)(r0 + 8) * 128 + col) =
                            __floats2half2_rn(c[m][n][2], c[m][n][3]);
                } else {        // P2 -> fp32 + bias
                    float bb0 = bias1[col];
                    float bb1 = bias1[col + 1];
                    if (r0 < M)
                        *(float2*)(C1 + (size_t)r0 * 128 + col) =
                            make_float2(c[m][n][0] + bb0, c[m][n][1] + bb1);
                    if (r0 + 8 < M)
                        *(float2*)(C1 + (size_t)(r0 + 8) * 128 + col) =
                            make_float2(c[m][n][2] + bb0, c[m][n][3] + bb1);
                }
            }
        }
    }
}

// ---------------- edge message + aggregation (warp per dst node) -------------
#define EDGE_BLK 64

__device__ __forceinline__ float4 loadP1h(const __half* __restrict__ P1,
                                          int s, int c4) {
    uint2 raw = *(const uint2*)(P1 + (size_t)s * HID + c4);
    __half2 h0 = *reinterpret_cast<__half2*>(&raw.x);
    __half2 h1 = *reinterpret_cast<__half2*>(&raw.y);
    float2 f0 = __half22float2(h0);
    float2 f1 = __half22float2(h1);
    return make_float4(f0.x, f0.y, f1.x, f1.y);
}

#define EDGE_ONE(p1v, eav)                                                        \
    do {                                                                          \
        float mx = (p1v).x + p2.x + (eav).x * w0.x + (eav).y * w1.x +             \
                   (eav).z * w2.x + (eav).w * w3.x;                               \
        float my = (p1v).y + p2.y + (eav).x * w0.y + (eav).y * w1.y +             \
                   (eav).z * w2.y + (eav).w * w3.y;                               \
        float mz = (p1v).z + p2.z + (eav).x * w0.z + (eav).y * w1.z +             \
                   (eav).z * w2.z + (eav).w * w3.z;                               \
        float mw = (p1v).w + p2.w + (eav).x * w0.w + (eav).y * w1.w +             \
                   (eav).z * w2.w + (eav).w * w3.w;                               \
        acc.x += fmaxf(mx, 0.f); acc.y += fmaxf(my, 0.f);                         \
        acc.z += fmaxf(mz, 0.f); acc.w += fmaxf(mw, 0.f);                         \
    } while (0)

#define EDGE_ACCUM_BODY                                                           \
    float4 acc = make_float4(0.f, 0.f, 0.f, 0.f);                                 \
    int e0 = g_off[v];                                                            \
    int e1 = g_off[v + 1];                                                        \
    int e  = e0;                                                                  \
    for (; e + 7 < e1; e += 8) {                                                  \
        int    s[8];                                                              \
        float4 q[8], aa[8];                                                       \
        _Pragma("unroll")                                                         \
        for (int i = 0; i < 8; ++i) s[i] = __ldg(&g_csr_src[e + i]);              \
        _Pragma("unroll")                                                         \
        for (int i = 0; i < 8; ++i) q[i] = loadP1h(P1, s[i], c4);                 \
        _Pragma("unroll")                                                         \
        for (int i = 0; i < 8; ++i) aa[i] = g_csr_ea[e + i];                      \
        _Pragma("unroll")                                                         \
        for (int i = 0; i < 8; ++i) EDGE_ONE(q[i], aa[i]);                        \
    }                                                                             \
    for (; e + 3 < e1; e += 4) {                                                  \
        int    s[4];                                                              \
        float4 q[4], aa[4];                                                       \
        _Pragma("unroll")                                                         \
        for (int i = 0; i < 4; ++i) s[i] = __ldg(&g_csr_src[e + i]);              \
        _Pragma("unroll")                                                         \
        for (int i = 0; i < 4; ++i) q[i] = loadP1h(P1, s[i], c4);                 \
        _Pragma("unroll")                                                         \
        for (int i = 0; i < 4; ++i) aa[i] = g_csr_ea[e + i];                      \
        _Pragma("unroll")                                                         \
        for (int i = 0; i < 4; ++i) EDGE_ONE(q[i], aa[i]);                        \
    }                                                                             \
    for (; e < e1; ++e) {                                                         \
        int    s  = __ldg(&g_csr_src[e]);                                         \
        float4 q  = loadP1h(P1, s, c4);                                           \
        float4 aa = g_csr_ea[e];                                                  \
        EDGE_ONE(q, aa);                                                          \
    }

__global__ __launch_bounds__(EDGE_BLK)
void edge_msg_kernel(const __half* __restrict__ P1, const float* __restrict__ P2,
                     const float* __restrict__ W3 /* [4,128] */) {
    int warp = (blockIdx.x * blockDim.x + threadIdx.x) >> 5;
    int lane = threadIdx.x & 31;
    if (warp >= N_NODES) return;
    int v = warp;
    int c4 = lane * 4;

    float4 w0 = *(const float4*)(W3 + 0 * HID + c4);
    float4 w1 = *(const float4*)(W3 + 1 * HID + c4);
    float4 w2 = *(const float4*)(W3 + 2 * HID + c4);
    float4 w3 = *(const float4*)(W3 + 3 * HID + c4);
    float4 p2 = *(const float4*)(P2 + (size_t)v * HID + c4);

    EDGE_ACCUM_BODY

    float4 xv = *(float4*)(g_x + (size_t)v * HID + c4);
    xv.x += acc.x; xv.y += acc.y; xv.z += acc.z; xv.w += acc.w;
    *(float4*)(g_x + (size_t)v * HID + c4) = xv;
}

// last layer: fuse output projection; never writes g_x (saves full RW pass)
__global__ __launch_bounds__(EDGE_BLK)
void edge_msg_out_kernel(const __half* __restrict__ P1, const float* __restrict__ P2,
                         const float* __restrict__ W3,
                         const float* __restrict__ Wout,
                         const float* __restrict__ bout,
                         float* __restrict__ out) {
    int warp = (blockIdx.x * blockDim.x + threadIdx.x) >> 5;
    int lane = threadIdx.x & 31;
    if (warp >= N_NODES) return;
    int v = warp;
    int c4 = lane * 4;

    float4 w0 = *(const float4*)(W3 + 0 * HID + c4);
    float4 w1 = *(const float4*)(W3 + 1 * HID + c4);
    float4 w2 = *(const float4*)(W3 + 2 * HID + c4);
    float4 w3 = *(const float4*)(W3 + 3 * HID + c4);
    float4 p2 = *(const float4*)(P2 + (size_t)v * HID + c4);

    EDGE_ACCUM_BODY

    float4 xv = *(float4*)(g_x + (size_t)v * HID + c4);
    xv.x += acc.x; xv.y += acc.y; xv.z += acc.z; xv.w += acc.w;

    // output projection from in-register xv; lane owns dims c4..c4+3
    float s0 = xv.x * Wout[(c4 + 0) * 3 + 0] + xv.y * Wout[(c4 + 1) * 3 + 0]
             + xv.z * Wout[(c4 + 2) * 3 + 0] + xv.w * Wout[(c4 + 3) * 3 + 0];
    float s1 = xv.x * Wout[(c4 + 0) * 3 + 1] + xv.y * Wout[(c4 + 1) * 3 + 1]
             + xv.z * Wout[(c4 + 2) * 3 + 1] + xv.w * Wout[(c4 + 3) * 3 + 1];
    float s2 = xv.x * Wout[(c4 + 0) * 3 + 2] + xv.y * Wout[(c4 + 1) * 3 + 2]
             + xv.z * Wout[(c4 + 2) * 3 + 2] + xv.w * Wout[(c4 + 3) * 3 + 2];
    #pragma unroll
    for (int o = 16; o > 0; o >>= 1) {
        s0 += __shfl_xor_sync(0xFFFFFFFFu, s0, o);
        s1 += __shfl_xor_sync(0xFFFFFFFFu, s1, o);
        s2 += __shfl_xor_sync(0xFFFFFFFFu, s2, o);
    }
    if (lane == 0) {
        out[v * 3 + 0] = s0 + bout[0];
        out[v * 3 + 1] = s1 + bout[1];
        out[v * 3 + 2] = s2 + bout[2];
    }
}

// ---------------- launch: fork-join graph (CSR chain || GEMM chain) ----------
extern "C" void kernel_launch(void* const* d_in, const int* in_sizes, int n_in,
                              void* d_out, int out_size) {
    const float* h     = (const float*)d_in[0];
    const int*   ei    = (const int*)  d_in[1];
    const float* ea    = (const float*)d_in[2];
    const float* W_in  = (const float*)d_in[3];
    const float* b_in  = (const float*)d_in[4];
    const float* W_msg = (const float*)d_in[5];
    const float* b_msg = (const float*)d_in[6];
    const float* W_out = (const float*)d_in[7];
    const float* b_out = (const float*)d_in[8];
    float* out = (float*)d_out;

    float  *px, *pP2;
    __half *pP1h;
    uint2  *pBfrag;
    cudaGetSymbolAddress((void**)&px,    g_x);
    cudaGetSymbolAddress((void**)&pP1h,  g_P1h);
    cudaGetSymbolAddress((void**)&pP2,   g_P2);
    cudaGetSymbolAddress((void**)&pBfrag, g_Bfrag);

    const int EB = (N_EDGES + 255) / 256;
    const int SB = (N_NODES + 1023) / 1024;       // 49
    const int MT = (N_NODES + GBM - 1) / GBM;     // 391
    const int NODE_BLOCKS = (N_NODES * 32 + EDGE_BLK - 1) / EDGE_BLK;   // 25000

    // side stream + fork/join events (created per call; kernel_launch runs
    // only for the correctness pass and the capture pass, so the handful of
    // leaked handles is bounded and harmless)
    cudaStream_t s2;
    cudaStreamCreateWithFlags(&s2, cudaStreamNonBlocking);
    cudaEvent_t evFork, evJoin;
    cudaEventCreateWithFlags(&evFork, cudaEventDisableTiming);
    cudaEventCreateWithFlags(&evJoin, cudaEventDisableTiming);

    // ---- fork: CSR chain on s2, GEMM chain on the capturing (default) stream
    cudaEventRecord(evFork, 0);
    cudaStreamWaitEvent(s2, evFork, 0);

    // CSR branch (independent of all GEMM work)
    count_deg_kernel<<<EB, 256, 0, s2>>>(ei);     // g_deg zeroed by prior replay/load
    scan_local_kernel<<<SB, 1024, 0, s2>>>();
    scan_add_kernel<<<SB, 1024, 0, s2>>>();       // also re-zeroes g_deg
    fill_csr_kernel<<<EB, 256, 0, s2>>>(ei, ea);
    cudaEventRecord(evJoin, s2);

    // GEMM branch
    prep_bfrag_kernel<<<160, 256>>>(W_in, W_msg);
    gemm_in_reg_kernel<<<MT, 256>>>(h, b_in, px, N_NODES);
    gemm_layer_reg_kernel<<<MT, 256>>>(px, pBfrag, b_msg, pP1h, pP2, N_NODES);

    // ---- join before first edge kernel (needs CSR + P1/P2)
    cudaStreamWaitEvent(0, evJoin, 0);

    for (int l = 0; l < N_LAYERS; ++l) {
        const float* Wl = W_msg + (size_t)l * (2 * HID + EDGE_DIM) * HID;
        if (l > 0) {
            gemm_layer_reg_kernel<<<MT, 256>>>(px,
                                               pBfrag + (size_t)l * 2 * 16 * 8 * 32,
                                               b_msg + l * HID,
                                               pP1h, pP2, N_NODES);
        }
        if (l < N_LAYERS - 1) {
            edge_msg_kernel<<<NODE_BLOCKS, EDGE_BLK>>>(pP1h, pP2,
                                                       Wl + 2 * HID * HID);
        } else {
            edge_msg_out_kernel<<<NODE_BLOCKS, EDGE_BLK>>>(pP1h, pP2,
                                                           Wl + 2 * HID * HID,
                                                           W_out, b_out, out);
        }
    }
}